// round 7
// baseline (speedup 1.0000x reference)
#include <cuda_runtime.h>
#include <cuda_bf16.h>
#include <math.h>
#include <stdint.h>

// ---------------- problem constants ----------------
#define BB 2
#define LL 1024
#define DM 512
#define DI 1024
#define RK 32
#define NS 16
#define MTOK (BB*LL)          // 2048 tokens
#define KSPLIT 8              // split-K factor for x_proj GEMM

// ---------------- scratch (static device arrays; no dynamic alloc) ---------
__device__ __align__(16) float g_xz[MTOK * 2 * DI];
__device__ __align__(16) float g_xs[MTOK * DI];
__device__ __align__(16) float g_dBC[MTOK * 64];
__device__ __align__(16) float g_dBC_part[KSPLIT * MTOK * 64];
__device__ __align__(16) float g_negA[DI * NS];
// bf16 hi/lo split buffers for tensor-core GEMMs
__device__ __align__(16) __nv_bfloat16 g_xh[MTOK * DM],  g_xl[MTOK * DM];
__device__ __align__(16) __nv_bfloat16 g_w1h[2*DI * DM], g_w1l[2*DI * DM];
__device__ __align__(16) __nv_bfloat16 g_w2h[DM * DI],   g_w2l[DM * DI];
__device__ __align__(16) __nv_bfloat16 g_ygh[MTOK * DI], g_ygl[MTOK * DI];

// ---------------- PTX helpers (arch-portable: sm_80+) ----------------
__device__ __forceinline__ uint32_t smem_u32(const void* p) {
    uint32_t a;
    asm("{ .reg .u64 t; cvta.to.shared.u64 t, %1; cvt.u32.u64 %0, t; }"
        : "=r"(a) : "l"(p));
    return a;
}

__device__ __forceinline__ void cp16(uint32_t saddr, const void* gptr) {
    asm volatile("cp.async.ca.shared.global [%0], [%1], 16;"
                 :: "r"(saddr), "l"(gptr));
}

__device__ __forceinline__ void ldsm_x4(uint32_t& r0, uint32_t& r1,
                                        uint32_t& r2, uint32_t& r3, uint32_t addr) {
    asm volatile("ldmatrix.sync.aligned.m8n8.x4.shared.b16 {%0,%1,%2,%3}, [%4];"
                 : "=r"(r0), "=r"(r1), "=r"(r2), "=r"(r3) : "r"(addr));
}

__device__ __forceinline__ void mma16816(float* d, const uint32_t* a, const uint32_t* b) {
    asm volatile(
        "mma.sync.aligned.m16n8k16.row.col.f32.bf16.bf16.f32 "
        "{%0,%1,%2,%3}, {%4,%5,%6,%7}, {%8,%9}, {%0,%1,%2,%3};"
        : "+f"(d[0]), "+f"(d[1]), "+f"(d[2]), "+f"(d[3])
        : "r"(a[0]), "r"(a[1]), "r"(a[2]), "r"(a[3]), "r"(b[0]), "r"(b[1]));
}

// ============ HMMA GEMM: C[M,N] = (Ah+Al)[M,K] * (Bh+Bl)[N,K]^T ============
// bf16x3 split: Ah*Bh + Ah*Bl + Al*Bh, fp32 accum. cp.async 2-stage pipeline.
template<int BM, int BN, int WMG, int WNG, int KTOT>
__global__ void __launch_bounds__(256)
mma_gemm(const __nv_bfloat16* __restrict__ Ah, const __nv_bfloat16* __restrict__ Al,
         const __nv_bfloat16* __restrict__ Bh, const __nv_bfloat16* __restrict__ Bl,
         float* __restrict__ C, int ldc)
{
    constexpr int BK  = 32;
    constexpr int LDT = 40;                 // smem row stride in bf16 (80B)
    constexpr int ATB = BM * LDT * 2;
    constexpr int BTB = BN * LDT * 2;
    constexpr int STAGE = 2*ATB + 2*BTB;
    constexpr int NIT = KTOT / BK;
    constexpr int WTM = BM / WMG;
    constexpr int WTN = BN / WNG;
    constexpr int MT  = WTM / 16;
    constexpr int NT  = WTN / 8;

    extern __shared__ char smem[];
    const uint32_t sbase = smem_u32(smem);
    const int tid  = threadIdx.x;
    const int lane = tid & 31;
    const int wid  = tid >> 5;
    const int wm   = wid % WMG;
    const int wn   = wid / WMG;
    const int row0 = blockIdx.y * BM;
    const int col0 = blockIdx.x * BN;

    float acc[MT][NT][4];
    #pragma unroll
    for (int i = 0; i < MT; i++)
        #pragma unroll
        for (int j = 0; j < NT; j++)
            #pragma unroll
            for (int q = 0; q < 4; q++) acc[i][j][q] = 0.f;

    auto load_stage = [&](int kb, int s) {
        const int k0 = kb * BK;
        const uint32_t sa = sbase + (uint32_t)s * STAGE;
        for (int i = tid; i < BM*4; i += 256) {
            int r = i >> 2, c = i & 3;
            uint32_t off = (uint32_t)r * (LDT*2) + c*16;
            cp16(sa + off,       Ah + (size_t)(row0+r)*KTOT + k0 + c*8);
            cp16(sa + ATB + off, Al + (size_t)(row0+r)*KTOT + k0 + c*8);
        }
        for (int i = tid; i < BN*4; i += 256) {
            int r = i >> 2, c = i & 3;
            uint32_t off = (uint32_t)r * (LDT*2) + c*16;
            cp16(sa + 2*ATB + off,       Bh + (size_t)(col0+r)*KTOT + k0 + c*8);
            cp16(sa + 2*ATB + BTB + off, Bl + (size_t)(col0+r)*KTOT + k0 + c*8);
        }
        asm volatile("cp.async.commit_group;" ::: "memory");
    };

    load_stage(0, 0);

    for (int kb = 0; kb < NIT; kb++) {
        if (kb + 1 < NIT) {
            load_stage(kb+1, (kb+1) & 1);
            asm volatile("cp.async.wait_group 1;" ::: "memory");
        } else {
            asm volatile("cp.async.wait_group 0;" ::: "memory");
        }
        __syncthreads();

        const uint32_t stA  = sbase + (uint32_t)(kb & 1) * STAGE;
        const uint32_t stAl = stA + ATB;
        const uint32_t stBh = stA + 2*ATB;
        const uint32_t stBl = stA + 2*ATB + BTB;

        #pragma unroll
        for (int ks = 0; ks < 2; ks++) {
            uint32_t ah[MT][4], al[MT][4], bh[NT][2], bl[NT][2];
            #pragma unroll
            for (int mt = 0; mt < MT; mt++) {
                int ar = wm*WTM + mt*16 + (lane & 15);
                int ac = ks*16 + (lane >> 4) * 8;
                uint32_t off = (uint32_t)ar*(LDT*2) + ac*2;
                ldsm_x4(ah[mt][0], ah[mt][1], ah[mt][2], ah[mt][3], stA  + off);
                ldsm_x4(al[mt][0], al[mt][1], al[mt][2], al[mt][3], stAl + off);
            }
            #pragma unroll
            for (int p = 0; p < NT/2; p++) {
                int br = wn*WTN + p*16 + (lane >> 4)*8 + (lane & 7);
                int bc = ks*16 + ((lane >> 3) & 1) * 8;
                uint32_t off = (uint32_t)br*(LDT*2) + bc*2;
                ldsm_x4(bh[2*p][0], bh[2*p][1], bh[2*p+1][0], bh[2*p+1][1], stBh + off);
                ldsm_x4(bl[2*p][0], bl[2*p][1], bl[2*p+1][0], bl[2*p+1][1], stBl + off);
            }
            #pragma unroll
            for (int mt = 0; mt < MT; mt++)
                #pragma unroll
                for (int nt = 0; nt < NT; nt++) {
                    mma16816(acc[mt][nt], ah[mt], bh[nt]);
                    mma16816(acc[mt][nt], ah[mt], bl[nt]);
                    mma16816(acc[mt][nt], al[mt], bh[nt]);
                }
        }
        __syncthreads();
    }

    #pragma unroll
    for (int mt = 0; mt < MT; mt++) {
        int r = row0 + wm*WTM + mt*16 + (lane >> 2);
        #pragma unroll
        for (int nt = 0; nt < NT; nt++) {
            int c = col0 + wn*WTN + nt*8 + (lane & 3)*2;
            *reinterpret_cast<float2*>(&C[(size_t)r*ldc + c]) =
                make_float2(acc[mt][nt][0], acc[mt][nt][1]);
            *reinterpret_cast<float2*>(&C[(size_t)(r+8)*ldc + c]) =
                make_float2(acc[mt][nt][2], acc[mt][nt][3]);
        }
    }
}

// ================= scalar helpers =================
union F2 { unsigned long long u; float2 f; };

__device__ __forceinline__ void ffma2(F2& d, const F2& a, const F2& b) {
    asm("fma.rn.f32x2 %0, %1, %2, %0;" : "+l"(d.u) : "l"(a.u), "l"(b.u));
}

__device__ __forceinline__ float softplusf(float v) {
    return (v > 20.f) ? v : log1pf(__expf(v));
}
__device__ __forceinline__ float siluf(float v) {
    return v / (1.f + __expf(-v));
}

__device__ __forceinline__ void split1(float v, __nv_bfloat16& hi, __nv_bfloat16& lo) {
    hi = __float2bfloat16(v);
    lo = __float2bfloat16(v - __bfloat162float(hi));
}

// ---------------- combined prep: weight/x splits + negA (one launch) -------
__global__ void prep_kernel(const float* __restrict__ x,
                            const float* __restrict__ in_proj_w,
                            const float* __restrict__ out_proj_w,
                            const float* __restrict__ A_log)
{
    int b = blockIdx.x;
    int t = threadIdx.x;
    if (b < 512) {                              // out_proj_w split (DM*DI)
        int i = b*256 + t;
        float4 v = ((const float4*)out_proj_w)[i];
        __nv_bfloat16 h0,h1,h2,h3,l0,l1,l2,l3;
        split1(v.x,h0,l0); split1(v.y,h1,l1); split1(v.z,h2,l2); split1(v.w,h3,l3);
        *(__nv_bfloat162*)(g_w2h + 4*i)     = __nv_bfloat162(h0,h1);
        *(__nv_bfloat162*)(g_w2h + 4*i + 2) = __nv_bfloat162(h2,h3);
        *(__nv_bfloat162*)(g_w2l + 4*i)     = __nv_bfloat162(l0,l1);
        *(__nv_bfloat162*)(g_w2l + 4*i + 2) = __nv_bfloat162(l2,l3);
    } else if (b < 1536) {                      // x split (MTOK*DM)
        int i = (b-512)*256 + t;
        float4 v = ((const float4*)x)[i];
        __nv_bfloat16 h0,h1,h2,h3,l0,l1,l2,l3;
        split1(v.x,h0,l0); split1(v.y,h1,l1); split1(v.z,h2,l2); split1(v.w,h3,l3);
        *(__nv_bfloat162*)(g_xh + 4*i)     = __nv_bfloat162(h0,h1);
        *(__nv_bfloat162*)(g_xh + 4*i + 2) = __nv_bfloat162(h2,h3);
        *(__nv_bfloat162*)(g_xl + 4*i)     = __nv_bfloat162(l0,l1);
        *(__nv_bfloat162*)(g_xl + 4*i + 2) = __nv_bfloat162(l2,l3);
    } else if (b < 2560) {                      // in_proj_w split (2*DI*DM)
        int i = (b-1536)*256 + t;
        float4 v = ((const float4*)in_proj_w)[i];
        __nv_bfloat16 h0,h1,h2,h3,l0,l1,l2,l3;
        split1(v.x,h0,l0); split1(v.y,h1,l1); split1(v.z,h2,l2); split1(v.w,h3,l3);
        *(__nv_bfloat162*)(g_w1h + 4*i)     = __nv_bfloat162(h0,h1);
        *(__nv_bfloat162*)(g_w1h + 4*i + 2) = __nv_bfloat162(h2,h3);
        *(__nv_bfloat162*)(g_w1l + 4*i)     = __nv_bfloat162(l0,l1);
        *(__nv_bfloat162*)(g_w1l + 4*i + 2) = __nv_bfloat162(l2,l3);
    } else {                                    // negA (DI*NS = 16384)
        int i = (b-2560)*256 + t;
        if (i < DI*NS) g_negA[i] = -__expf(A_log[i]);
    }
}

// ---------------- depthwise conv1d (K=3, SAME) + silu ----------------
__global__ void conv_silu_kernel(const float* __restrict__ w,
                                 const float* __restrict__ b)
{
    int d = blockIdx.x * blockDim.x + threadIdx.x;
    int m = blockIdx.y;
    int l = m & (LL - 1);
    float w0 = w[d*3+0], w1 = w[d*3+1], w2 = w[d*3+2];
    float xm = (l > 0)      ? g_xz[(size_t)(m-1)*2*DI + d] : 0.f;
    float x0 =                g_xz[(size_t)m    *2*DI + d];
    float xp = (l < LL-1)   ? g_xz[(size_t)(m+1)*2*DI + d] : 0.f;
    float v = fmaf(w0, xm, fmaf(w1, x0, fmaf(w2, xp, b[d])));
    g_xs[(size_t)m*DI + d] = siluf(v);
}

// ---------------- split-K NT GEMM for skinny x_proj (measured 22us) --------
template<int BM, int BN, int BK, int TM, int TN, int KC>
__global__ void __launch_bounds__((BM/TM)*(BN/TN))
gemm_nt_splitk(const float* __restrict__ A, const float* __restrict__ B,
               float* __restrict__ Cpart, int lda, int ldb)
{
    constexpr int THREADS = (BM/TM) * (BN/TN);
    constexpr int TXN = BN / TN;
    __shared__ __align__(16) float As[BK][BM];
    __shared__ __align__(16) float Bs[BK][BN];

    const int tid = threadIdx.x;
    const int tx  = tid % TXN;
    const int ty  = tid / TXN;
    const int row0   = blockIdx.y * BM;
    const int kchunk = blockIdx.x;
    const int kbase  = kchunk * KC;

    F2 acc[TM][TN/2];
    #pragma unroll
    for (int i = 0; i < TM; i++)
        #pragma unroll
        for (int j = 0; j < TN/2; j++) { acc[i][j].f.x = 0.f; acc[i][j].f.y = 0.f; }

    for (int k0 = kbase; k0 < kbase + KC; k0 += BK) {
        #pragma unroll
        for (int i = tid; i < BM*BK/4; i += THREADS) {
            int r = i / (BK/4), cv = i % (BK/4);
            float4 v = *reinterpret_cast<const float4*>(
                &A[(size_t)(row0 + r) * lda + k0 + cv*4]);
            As[cv*4+0][r] = v.x; As[cv*4+1][r] = v.y;
            As[cv*4+2][r] = v.z; As[cv*4+3][r] = v.w;
        }
        #pragma unroll
        for (int i = tid; i < BN*BK/4; i += THREADS) {
            int r = i / (BK/4), cv = i % (BK/4);
            float4 v = *reinterpret_cast<const float4*>(
                &B[(size_t)r * ldb + k0 + cv*4]);
            Bs[cv*4+0][r] = v.x; Bs[cv*4+1][r] = v.y;
            Bs[cv*4+2][r] = v.z; Bs[cv*4+3][r] = v.w;
        }
        __syncthreads();

        #pragma unroll
        for (int k = 0; k < BK; k++) {
            float a_frag[TM];
            F2 b_frag[TN/2];
            #pragma unroll
            for (int i = 0; i < TM; i++) a_frag[i] = As[k][ty*TM + i];
            #pragma unroll
            for (int j = 0; j < TN/2; j++)
                b_frag[j] = *reinterpret_cast<const F2*>(&Bs[k][tx*TN + 2*j]);
            #pragma unroll
            for (int i = 0; i < TM; i++) {
                F2 ad; ad.f.x = a_frag[i]; ad.f.y = a_frag[i];
                #pragma unroll
                for (int j = 0; j < TN/2; j++) ffma2(acc[i][j], ad, b_frag[j]);
            }
        }
        __syncthreads();
    }

    float* Cp = Cpart + (size_t)kchunk * MTOK * 64;
    #pragma unroll
    for (int i = 0; i < TM; i++) {
        int r = row0 + ty*TM + i;
        #pragma unroll
        for (int j = 0; j < TN/2; j++) {
            int c = tx*TN + 2*j;
            *reinterpret_cast<float2*>(&Cp[(size_t)r * 64 + c]) = acc[i][j].f;
        }
    }
}

__global__ void splitk_reduce_kernel() {
    int i = blockIdx.x * blockDim.x + threadIdx.x;
    if (i >= MTOK * 32) return;
    float2 s = make_float2(0.f, 0.f);
    #pragma unroll
    for (int c = 0; c < KSPLIT; c++) {
        float2 v = *reinterpret_cast<const float2*>(&g_dBC_part[(size_t)c*MTOK*64 + i*2]);
        s.x += v.x; s.y += v.y;
    }
    *reinterpret_cast<float2*>(&g_dBC[i*2]) = s;
}

// ---- fused: delta GEMM(K=32)+softplus + SSM + state fusion + y + gate -----
__global__ void ssm_fused_kernel(const float* __restrict__ h,
                                 const float* __restrict__ dtw,
                                 const float* __restrict__ dtb,
                                 const float* __restrict__ Dvec,
                                 const float* __restrict__ sf1w,
                                 const float* __restrict__ sf1b,
                                 const float* __restrict__ sf2w,
                                 const float* __restrict__ sf2b,
                                 const float* __restrict__ alpha,
                                 float* __restrict__ out_hn)
{
    int d = blockIdx.x * blockDim.x + threadIdx.x;
    int m = blockIdx.y;
    size_t md = (size_t)m * DI + d;

    __shared__ float dbc_s[64];
    if (threadIdx.x < 64) dbc_s[threadIdx.x] = g_dBC[(size_t)m * 64 + threadIdx.x];
    __syncthreads();

    // delta = softplus(dBC[m,0:32] . dtw[d,:] + dtb[d])   (K4 fused in)
    float acc = dtb[d];
    const float4* wp4 = reinterpret_cast<const float4*>(dtw + (size_t)d * RK);
    #pragma unroll
    for (int r = 0; r < 8; r++) {
        float4 w4 = wp4[r];
        acc = fmaf(w4.x, dbc_s[4*r+0], acc);
        acc = fmaf(w4.y, dbc_s[4*r+1], acc);
        acc = fmaf(w4.z, dbc_s[4*r+2], acc);
        acc = fmaf(w4.w, dbc_s[4*r+3], acc);
    }
    float dv  = softplusf(acc);
    float xsv = g_xs[md];
    float dx  = dv * xsv;

    // exp via powers: negA[d][s] ~= (s+1)*negA[d][0]; corrected, with fallback
    float na[16];
    const float4* nap = reinterpret_cast<const float4*>(g_negA + (size_t)d * NS);
    #pragma unroll
    for (int q = 0; q < 4; q++) {
        float4 v = nap[q];
        na[4*q+0] = v.x; na[4*q+1] = v.y; na[4*q+2] = v.z; na[4*q+3] = v.w;
    }
    float e0 = dv * na[0];
    float g  = __expf(e0);

    const float4* hp = reinterpret_cast<const float4*>(h + md * NS);
    float hv[16];
    #pragma unroll
    for (int q = 0; q < 4; q++) {
        float4 v = hp[q];
        hv[4*q+0] = v.x; hv[4*q+1] = v.y; hv[4*q+2] = v.z; hv[4*q+3] = v.w;
    }

    float hn[16];
    float p = 1.f;
    #pragma unroll
    for (int s = 0; s < 16; s++) {
        p *= g;                                   // p = g^(s+1)
        float x    = dv * na[s];
        float corr = x - (float)(s+1) * e0;
        float f = (fabsf(corr) < 1e-3f) ? p * (1.f + corr) : __expf(x);
        hn[s] = fmaf(f, hv[s], dx * dbc_s[32 + s]);
    }

    // state fusion: alpha0*(1x1) + alpha1*(3x3, pad 1) on 4x4 grid
    float a0 = alpha[0], a1 = alpha[1];
    float c1 = a0 * sf1w[d];
    float cb = fmaf(a0, sf1b[d], a1 * sf2b[d]);
    float w[9];
    #pragma unroll
    for (int i = 0; i < 9; i++) w[i] = sf2w[d*9 + i];

    float y = 0.f;
    float hf[16];
    #pragma unroll
    for (int r = 0; r < 4; r++) {
        #pragma unroll
        for (int c = 0; c < 4; c++) {
            float a2 = 0.f;
            #pragma unroll
            for (int ii = 0; ii < 3; ii++) {
                int rr = r + ii - 1;
                if (rr < 0 || rr > 3) continue;
                #pragma unroll
                for (int jj = 0; jj < 3; jj++) {
                    int cc = c + jj - 1;
                    if (cc < 0 || cc > 3) continue;
                    a2 = fmaf(w[ii*3 + jj], hn[rr*4 + cc], a2);
                }
            }
            float v = fmaf(c1, hn[r*4 + c], fmaf(a1, a2, cb));
            hf[r*4 + c] = v;
            y = fmaf(v, dbc_s[48 + r*4 + c], y);
        }
    }

    float4* op = reinterpret_cast<float4*>(out_hn + md * NS);
    #pragma unroll
    for (int q = 0; q < 4; q++)
        op[q] = make_float4(hf[4*q+0], hf[4*q+1], hf[4*q+2], hf[4*q+3]);

    y = fmaf(Dvec[d], xsv, y);
    float zv = g_xz[(size_t)m * 2 * DI + DI + d];
    float yv = y * siluf(zv);
    __nv_bfloat16 hh = __float2bfloat16(yv);
    g_ygh[md] = hh;
    g_ygl[md] = __float2bfloat16(yv - __bfloat162float(hh));
}

// ---------------- launch ----------------
extern "C" void kernel_launch(void* const* d_in, const int* in_sizes, int n_in,
                              void* d_out, int out_size)
{
    const float* x          = (const float*)d_in[0];
    const float* h          = (const float*)d_in[1];
    const float* in_proj_w  = (const float*)d_in[2];
    const float* conv1d_w   = (const float*)d_in[3];
    const float* conv1d_b   = (const float*)d_in[4];
    const float* x_proj_w   = (const float*)d_in[5];
    const float* dt_proj_w  = (const float*)d_in[6];
    const float* dt_proj_b  = (const float*)d_in[7];
    const float* A_log      = (const float*)d_in[8];
    const float* Dvec       = (const float*)d_in[9];
    const float* sf1_w      = (const float*)d_in[10];
    const float* sf1_b      = (const float*)d_in[11];
    const float* sf2_w      = (const float*)d_in[12];
    const float* sf2_b      = (const float*)d_in[13];
    const float* alpha      = (const float*)d_in[14];
    const float* out_proj_w = (const float*)d_in[15];

    float* out    = (float*)d_out;                    // [2048, 512]
    float* out_hn = (float*)d_out + (size_t)MTOK*DM;  // [2048, 1024, 16]

    float *xz, *dbc_part, *xs;
    cudaGetSymbolAddress((void**)&xz,       g_xz);
    cudaGetSymbolAddress((void**)&xs,       g_xs);
    cudaGetSymbolAddress((void**)&dbc_part, g_dBC_part);

    __nv_bfloat16 *xh, *xl, *w1h, *w1l, *w2h, *w2l, *ygh, *ygl;
    cudaGetSymbolAddress((void**)&xh,  g_xh);
    cudaGetSymbolAddress((void**)&xl,  g_xl);
    cudaGetSymbolAddress((void**)&w1h, g_w1h);
    cudaGetSymbolAddress((void**)&w1l, g_w1l);
    cudaGetSymbolAddress((void**)&w2h, g_w2h);
    cudaGetSymbolAddress((void**)&w2l, g_w2l);
    cudaGetSymbolAddress((void**)&ygh, g_ygh);
    cudaGetSymbolAddress((void**)&ygl, g_ygl);

    constexpr int SMEM_K1 = 2 * (2*128*40*2 + 2*128*40*2);   // 81920
    constexpr int SMEM_K6 = 2 * (2*64*40*2  + 2*128*40*2);   // 61440
    cudaFuncSetAttribute(mma_gemm<128,128,4,2,512>,
                         cudaFuncAttributeMaxDynamicSharedMemorySize, SMEM_K1);
    cudaFuncSetAttribute(mma_gemm<64,128,2,4,1024>,
                         cudaFuncAttributeMaxDynamicSharedMemorySize, SMEM_K6);

    // L1: prep (all splits + negA in one launch)
    prep_kernel<<<2624, 256>>>(x, in_proj_w, out_proj_w, A_log);

    // L2 (K1): xz = x @ in_proj_w^T  [2048,2048,K=512] — HMMA bf16x3
    mma_gemm<128,128,4,2,512><<<dim3(2*DI/128, MTOK/128), 256, SMEM_K1>>>(
        xh, xl, w1h, w1l, xz, 2*DI);

    // L3 (K2): xs = silu(dwconv1d(xc))
    conv_silu_kernel<<<dim3(4, MTOK), 256>>>(conv1d_w, conv1d_b);

    // L4 (K3): dBC = xs @ x_proj_w^T  (split-K x8)
    gemm_nt_splitk<64,64,16,4,4,128><<<dim3(KSPLIT, MTOK/64), 256>>>(
        xs, x_proj_w, dbc_part, DI, DI);
    // L5: reduce
    splitk_reduce_kernel<<<(MTOK*32 + 255)/256, 256>>>();

    // L6 (K5): fused delta + SSM + state fusion + y + gate
    ssm_fused_kernel<<<dim3(4, MTOK), 256>>>(
        h, dt_proj_w, dt_proj_b, Dvec, sf1_w, sf1_b, sf2_w, sf2_b, alpha, out_hn);

    // L7 (K6): out = (y * silu(z)) @ out_proj_w^T — HMMA bf16x3
    mma_gemm<64,128,2,4,1024><<<dim3(DM/128, MTOK/64), 256, SMEM_K6>>>(
        ygh, ygl, w2h, w2l, out, DM);
}

// round 8
// speedup vs baseline: 1.2365x; 1.2365x over previous
#include <cuda_runtime.h>
#include <cuda_bf16.h>
#include <math.h>
#include <stdint.h>

// ---------------- problem constants ----------------
#define BB 2
#define LL 1024
#define DM 512
#define DI 1024
#define RK 32
#define NS 16
#define MTOK (BB*LL)          // 2048 tokens
#define KSPLIT 8              // split-K factor for x_proj GEMM

// ---------------- scratch (static device arrays; no dynamic alloc) ---------
__device__ __align__(16) float g_xz[MTOK * 2 * DI];
__device__ __align__(16) float g_xs[MTOK * DI];
__device__ __align__(16) float g_dBC[MTOK * 64];
__device__ __align__(16) float g_dBC_part[KSPLIT * MTOK * 64];
__device__ __align__(16) float g_negA[DI * NS];
__device__ __align__(16) float g_dtwT[RK * DI];         // dt_proj_w transposed [32][1024]
// bf16 hi/lo split buffers for tensor-core GEMMs
__device__ __align__(16) __nv_bfloat16 g_xh[MTOK * DM],  g_xl[MTOK * DM];
__device__ __align__(16) __nv_bfloat16 g_w1h[2*DI * DM], g_w1l[2*DI * DM];
__device__ __align__(16) __nv_bfloat16 g_w2h[DM * DI],   g_w2l[DM * DI];
__device__ __align__(16) __nv_bfloat16 g_ygh[MTOK * DI], g_ygl[MTOK * DI];

// ---------------- PTX helpers (arch-portable: sm_80+) ----------------
__device__ __forceinline__ uint32_t smem_u32(const void* p) {
    uint32_t a;
    asm("{ .reg .u64 t; cvta.to.shared.u64 t, %1; cvt.u32.u64 %0, t; }"
        : "=r"(a) : "l"(p));
    return a;
}

__device__ __forceinline__ void cp16(uint32_t saddr, const void* gptr) {
    asm volatile("cp.async.ca.shared.global [%0], [%1], 16;"
                 :: "r"(saddr), "l"(gptr));
}

__device__ __forceinline__ void ldsm_x4(uint32_t& r0, uint32_t& r1,
                                        uint32_t& r2, uint32_t& r3, uint32_t addr) {
    asm volatile("ldmatrix.sync.aligned.m8n8.x4.shared.b16 {%0,%1,%2,%3}, [%4];"
                 : "=r"(r0), "=r"(r1), "=r"(r2), "=r"(r3) : "r"(addr));
}

__device__ __forceinline__ void mma16816(float* d, const uint32_t* a, const uint32_t* b) {
    asm volatile(
        "mma.sync.aligned.m16n8k16.row.col.f32.bf16.bf16.f32 "
        "{%0,%1,%2,%3}, {%4,%5,%6,%7}, {%8,%9}, {%0,%1,%2,%3};"
        : "+f"(d[0]), "+f"(d[1]), "+f"(d[2]), "+f"(d[3])
        : "r"(a[0]), "r"(a[1]), "r"(a[2]), "r"(a[3]), "r"(b[0]), "r"(b[1]));
}

// ============ HMMA GEMM: C[M,N] = (Ah+Al)[M,K] * (Bh+Bl)[N,K]^T ============
// bf16x3 split: Ah*Bh + Ah*Bl + Al*Bh, fp32 accum. cp.async 2-stage pipeline.
template<int BM, int BN, int WMG, int WNG, int KTOT>
__global__ void __launch_bounds__(256)
mma_gemm(const __nv_bfloat16* __restrict__ Ah, const __nv_bfloat16* __restrict__ Al,
         const __nv_bfloat16* __restrict__ Bh, const __nv_bfloat16* __restrict__ Bl,
         float* __restrict__ C, int ldc)
{
    constexpr int BK  = 32;
    constexpr int LDT = 40;                 // smem row stride in bf16 (80B)
    constexpr int ATB = BM * LDT * 2;
    constexpr int BTB = BN * LDT * 2;
    constexpr int STAGE = 2*ATB + 2*BTB;
    constexpr int NIT = KTOT / BK;
    constexpr int WTM = BM / WMG;
    constexpr int WTN = BN / WNG;
    constexpr int MT  = WTM / 16;
    constexpr int NT  = WTN / 8;

    extern __shared__ char smem[];
    const uint32_t sbase = smem_u32(smem);
    const int tid  = threadIdx.x;
    const int lane = tid & 31;
    const int wid  = tid >> 5;
    const int wm   = wid % WMG;
    const int wn   = wid / WMG;
    const int row0 = blockIdx.y * BM;
    const int col0 = blockIdx.x * BN;

    float acc[MT][NT][4];
    #pragma unroll
    for (int i = 0; i < MT; i++)
        #pragma unroll
        for (int j = 0; j < NT; j++)
            #pragma unroll
            for (int q = 0; q < 4; q++) acc[i][j][q] = 0.f;

    auto load_stage = [&](int kb, int s) {
        const int k0 = kb * BK;
        const uint32_t sa = sbase + (uint32_t)s * STAGE;
        for (int i = tid; i < BM*4; i += 256) {
            int r = i >> 2, c = i & 3;
            uint32_t off = (uint32_t)r * (LDT*2) + c*16;
            cp16(sa + off,       Ah + (size_t)(row0+r)*KTOT + k0 + c*8);
            cp16(sa + ATB + off, Al + (size_t)(row0+r)*KTOT + k0 + c*8);
        }
        for (int i = tid; i < BN*4; i += 256) {
            int r = i >> 2, c = i & 3;
            uint32_t off = (uint32_t)r * (LDT*2) + c*16;
            cp16(sa + 2*ATB + off,       Bh + (size_t)(col0+r)*KTOT + k0 + c*8);
            cp16(sa + 2*ATB + BTB + off, Bl + (size_t)(col0+r)*KTOT + k0 + c*8);
        }
        asm volatile("cp.async.commit_group;" ::: "memory");
    };

    load_stage(0, 0);

    for (int kb = 0; kb < NIT; kb++) {
        if (kb + 1 < NIT) {
            load_stage(kb+1, (kb+1) & 1);
            asm volatile("cp.async.wait_group 1;" ::: "memory");
        } else {
            asm volatile("cp.async.wait_group 0;" ::: "memory");
        }
        __syncthreads();

        const uint32_t stA  = sbase + (uint32_t)(kb & 1) * STAGE;
        const uint32_t stAl = stA + ATB;
        const uint32_t stBh = stA + 2*ATB;
        const uint32_t stBl = stA + 2*ATB + BTB;

        #pragma unroll
        for (int ks = 0; ks < 2; ks++) {
            uint32_t ah[MT][4], al[MT][4], bh[NT][2], bl[NT][2];
            #pragma unroll
            for (int mt = 0; mt < MT; mt++) {
                int ar = wm*WTM + mt*16 + (lane & 15);
                int ac = ks*16 + (lane >> 4) * 8;
                uint32_t off = (uint32_t)ar*(LDT*2) + ac*2;
                ldsm_x4(ah[mt][0], ah[mt][1], ah[mt][2], ah[mt][3], stA  + off);
                ldsm_x4(al[mt][0], al[mt][1], al[mt][2], al[mt][3], stAl + off);
            }
            #pragma unroll
            for (int p = 0; p < NT/2; p++) {
                int br = wn*WTN + p*16 + (lane >> 4)*8 + (lane & 7);
                int bc = ks*16 + ((lane >> 3) & 1) * 8;
                uint32_t off = (uint32_t)br*(LDT*2) + bc*2;
                ldsm_x4(bh[2*p][0], bh[2*p][1], bh[2*p+1][0], bh[2*p+1][1], stBh + off);
                ldsm_x4(bl[2*p][0], bl[2*p][1], bl[2*p+1][0], bl[2*p+1][1], stBl + off);
            }
            #pragma unroll
            for (int mt = 0; mt < MT; mt++)
                #pragma unroll
                for (int nt = 0; nt < NT; nt++) {
                    mma16816(acc[mt][nt], ah[mt], bh[nt]);
                    mma16816(acc[mt][nt], ah[mt], bl[nt]);
                    mma16816(acc[mt][nt], al[mt], bh[nt]);
                }
        }
        __syncthreads();
    }

    #pragma unroll
    for (int mt = 0; mt < MT; mt++) {
        int r = row0 + wm*WTM + mt*16 + (lane >> 2);
        #pragma unroll
        for (int nt = 0; nt < NT; nt++) {
            int c = col0 + wn*WTN + nt*8 + (lane & 3)*2;
            *reinterpret_cast<float2*>(&C[(size_t)r*ldc + c]) =
                make_float2(acc[mt][nt][0], acc[mt][nt][1]);
            *reinterpret_cast<float2*>(&C[(size_t)(r+8)*ldc + c]) =
                make_float2(acc[mt][nt][2], acc[mt][nt][3]);
        }
    }
}

// ---------------- fp32 -> bf16 hi/lo split ----------------
__global__ void split_bf16_kernel(const float* __restrict__ src,
                                  __nv_bfloat16* __restrict__ hi,
                                  __nv_bfloat16* __restrict__ lo, int n4)
{
    int i = blockIdx.x * blockDim.x + threadIdx.x;
    if (i >= n4) return;
    float4 v = ((const float4*)src)[i];
    __nv_bfloat16 h0 = __float2bfloat16(v.x), h1 = __float2bfloat16(v.y);
    __nv_bfloat16 h2 = __float2bfloat16(v.z), h3 = __float2bfloat16(v.w);
    __nv_bfloat16 l0 = __float2bfloat16(v.x - __bfloat162float(h0));
    __nv_bfloat16 l1 = __float2bfloat16(v.y - __bfloat162float(h1));
    __nv_bfloat16 l2 = __float2bfloat16(v.z - __bfloat162float(h2));
    __nv_bfloat16 l3 = __float2bfloat16(v.w - __bfloat162float(h3));
    *(__nv_bfloat162*)(hi + 4*i)     = __nv_bfloat162(h0, h1);
    *(__nv_bfloat162*)(hi + 4*i + 2) = __nv_bfloat162(h2, h3);
    *(__nv_bfloat162*)(lo + 4*i)     = __nv_bfloat162(l0, l1);
    *(__nv_bfloat162*)(lo + 4*i + 2) = __nv_bfloat162(l2, l3);
}

// ================= scalar helpers =================
union F2 { unsigned long long u; float2 f; };

__device__ __forceinline__ void ffma2(F2& d, const F2& a, const F2& b) {
    asm("fma.rn.f32x2 %0, %1, %2, %0;" : "+l"(d.u) : "l"(a.u), "l"(b.u));
}

__device__ __forceinline__ float softplusf(float v) {
    return (v > 20.f) ? v : log1pf(expf(v));
}
__device__ __forceinline__ float siluf(float v) {
    return v / (1.f + __expf(-v));
}

// ---------------- negA + dt_proj_w transpose (one launch) ----------------
__global__ void negA_dtw_kernel(const float* __restrict__ A_log,
                                const float* __restrict__ dtw)
{
    int b = blockIdx.x;
    int t = threadIdx.x;
    if (b < 64) {                        // negA: DI*NS = 16384
        int i = b*256 + t;
        g_negA[i] = -expf(A_log[i]);
    } else {                             // transpose dtw [DI][RK] -> [RK][DI]
        int i = (b-64)*256 + t;          // 0 .. RK*DI-1
        int k = i / DI, d = i % DI;      // coalesced write to g_dtwT
        g_dtwT[i] = dtw[(size_t)d * RK + k];
    }
}

// ---------------- depthwise conv1d (K=3, SAME) + silu ----------------
__global__ void conv_silu_kernel(const float* __restrict__ w,
                                 const float* __restrict__ b)
{
    int d = blockIdx.x * blockDim.x + threadIdx.x;
    int m = blockIdx.y;
    int l = m & (LL - 1);
    float w0 = w[d*3+0], w1 = w[d*3+1], w2 = w[d*3+2];
    float xm = (l > 0)      ? g_xz[(size_t)(m-1)*2*DI + d] : 0.f;
    float x0 =                g_xz[(size_t)m    *2*DI + d];
    float xp = (l < LL-1)   ? g_xz[(size_t)(m+1)*2*DI + d] : 0.f;
    float v = fmaf(w0, xm, fmaf(w1, x0, fmaf(w2, xp, b[d])));
    g_xs[(size_t)m*DI + d] = siluf(v);
}

// ---------------- split-K NT GEMM for skinny x_proj ----------------
template<int BM, int BN, int BK, int TM, int TN, int KC>
__global__ void __launch_bounds__((BM/TM)*(BN/TN))
gemm_nt_splitk(const float* __restrict__ A, const float* __restrict__ B,
               float* __restrict__ Cpart, int lda, int ldb)
{
    constexpr int THREADS = (BM/TM) * (BN/TN);
    constexpr int TXN = BN / TN;
    __shared__ __align__(16) float As[BK][BM];
    __shared__ __align__(16) float Bs[BK][BN];

    const int tid = threadIdx.x;
    const int tx  = tid % TXN;
    const int ty  = tid / TXN;
    const int row0   = blockIdx.y * BM;
    const int kchunk = blockIdx.x;
    const int kbase  = kchunk * KC;

    F2 acc[TM][TN/2];
    #pragma unroll
    for (int i = 0; i < TM; i++)
        #pragma unroll
        for (int j = 0; j < TN/2; j++) { acc[i][j].f.x = 0.f; acc[i][j].f.y = 0.f; }

    for (int k0 = kbase; k0 < kbase + KC; k0 += BK) {
        #pragma unroll
        for (int i = tid; i < BM*BK/4; i += THREADS) {
            int r = i / (BK/4), cv = i % (BK/4);
            float4 v = *reinterpret_cast<const float4*>(
                &A[(size_t)(row0 + r) * lda + k0 + cv*4]);
            As[cv*4+0][r] = v.x; As[cv*4+1][r] = v.y;
            As[cv*4+2][r] = v.z; As[cv*4+3][r] = v.w;
        }
        #pragma unroll
        for (int i = tid; i < BN*BK/4; i += THREADS) {
            int r = i / (BK/4), cv = i % (BK/4);
            float4 v = *reinterpret_cast<const float4*>(
                &B[(size_t)r * ldb + k0 + cv*4]);
            Bs[cv*4+0][r] = v.x; Bs[cv*4+1][r] = v.y;
            Bs[cv*4+2][r] = v.z; Bs[cv*4+3][r] = v.w;
        }
        __syncthreads();

        #pragma unroll
        for (int k = 0; k < BK; k++) {
            float a_frag[TM];
            F2 b_frag[TN/2];
            #pragma unroll
            for (int i = 0; i < TM; i++) a_frag[i] = As[k][ty*TM + i];
            #pragma unroll
            for (int j = 0; j < TN/2; j++)
                b_frag[j] = *reinterpret_cast<const F2*>(&Bs[k][tx*TN + 2*j]);
            #pragma unroll
            for (int i = 0; i < TM; i++) {
                F2 ad; ad.f.x = a_frag[i]; ad.f.y = a_frag[i];
                #pragma unroll
                for (int j = 0; j < TN/2; j++) ffma2(acc[i][j], ad, b_frag[j]);
            }
        }
        __syncthreads();
    }

    float* Cp = Cpart + (size_t)kchunk * MTOK * 64;
    #pragma unroll
    for (int i = 0; i < TM; i++) {
        int r = row0 + ty*TM + i;
        #pragma unroll
        for (int j = 0; j < TN/2; j++) {
            int c = tx*TN + 2*j;
            *reinterpret_cast<float2*>(&Cp[(size_t)r * 64 + c]) = acc[i][j].f;
        }
    }
}

__global__ void splitk_reduce_kernel() {
    int i = blockIdx.x * blockDim.x + threadIdx.x;
    if (i >= MTOK * 32) return;
    float2 s = make_float2(0.f, 0.f);
    #pragma unroll
    for (int c = 0; c < KSPLIT; c++) {
        float2 v = *reinterpret_cast<const float2*>(&g_dBC_part[(size_t)c*MTOK*64 + i*2]);
        s.x += v.x; s.y += v.y;
    }
    *reinterpret_cast<float2*>(&g_dBC[i*2]) = s;
}

// ---- fused: delta(coalesced dtwT dot) + SSM + state fusion + y + gate -----
// R6 structure; only delta computation added (coalesced), exp = plain __expf.
__global__ void ssm_fused_kernel(const float* __restrict__ h,
                                 const float* __restrict__ dtb,
                                 const float* __restrict__ Dvec,
                                 const float* __restrict__ sf1w,
                                 const float* __restrict__ sf1b,
                                 const float* __restrict__ sf2w,
                                 const float* __restrict__ sf2b,
                                 const float* __restrict__ alpha,
                                 float* __restrict__ out_hn)
{
    int d = blockIdx.x * blockDim.x + threadIdx.x;
    int m = blockIdx.y;
    size_t md = (size_t)m * DI + d;

    __shared__ float dbc_s[64];
    if (threadIdx.x < 64) dbc_s[threadIdx.x] = g_dBC[(size_t)m * 64 + threadIdx.x];
    __syncthreads();

    // delta = softplus(dBC[m,0:32] . dtwT[:,d] + dtb[d]) — coalesced over d
    float acc = dtb[d];
    #pragma unroll
    for (int k = 0; k < RK; k++)
        acc = fmaf(g_dtwT[k*DI + d], dbc_s[k], acc);
    float dv  = softplusf(acc);
    float xsv = g_xs[md];
    float dx  = dv * xsv;

    const float4* hp = reinterpret_cast<const float4*>(h + md * NS);
    float hn[16];
    #pragma unroll
    for (int q = 0; q < 4; q++) {
        float4 hv = hp[q];
        float na0 = g_negA[d*NS + 4*q + 0];
        float na1 = g_negA[d*NS + 4*q + 1];
        float na2 = g_negA[d*NS + 4*q + 2];
        float na3 = g_negA[d*NS + 4*q + 3];
        hn[4*q+0] = fmaf(__expf(dv*na0), hv.x, dx * dbc_s[32 + 4*q + 0]);
        hn[4*q+1] = fmaf(__expf(dv*na1), hv.y, dx * dbc_s[32 + 4*q + 1]);
        hn[4*q+2] = fmaf(__expf(dv*na2), hv.z, dx * dbc_s[32 + 4*q + 2]);
        hn[4*q+3] = fmaf(__expf(dv*na3), hv.w, dx * dbc_s[32 + 4*q + 3]);
    }

    float a0 = alpha[0], a1 = alpha[1];
    float c1 = a0 * sf1w[d];
    float cb = fmaf(a0, sf1b[d], a1 * sf2b[d]);
    float w[9];
    #pragma unroll
    for (int i = 0; i < 9; i++) w[i] = sf2w[d*9 + i];

    float y = 0.f;
    float hf[16];
    #pragma unroll
    for (int r = 0; r < 4; r++) {
        #pragma unroll
        for (int c = 0; c < 4; c++) {
            float a2 = 0.f;
            #pragma unroll
            for (int ii = 0; ii < 3; ii++) {
                int rr = r + ii - 1;
                if (rr < 0 || rr > 3) continue;
                #pragma unroll
                for (int jj = 0; jj < 3; jj++) {
                    int cc = c + jj - 1;
                    if (cc < 0 || cc > 3) continue;
                    a2 = fmaf(w[ii*3 + jj], hn[rr*4 + cc], a2);
                }
            }
            float v = fmaf(c1, hn[r*4 + c], fmaf(a1, a2, cb));
            hf[r*4 + c] = v;
            y = fmaf(v, dbc_s[48 + r*4 + c], y);
        }
    }

    float4* op = reinterpret_cast<float4*>(out_hn + md * NS);
    #pragma unroll
    for (int q = 0; q < 4; q++)
        op[q] = make_float4(hf[4*q+0], hf[4*q+1], hf[4*q+2], hf[4*q+3]);

    y = fmaf(Dvec[d], xsv, y);
    float zv = g_xz[(size_t)m * 2 * DI + DI + d];
    float yv = y * siluf(zv);
    __nv_bfloat16 hh = __float2bfloat16(yv);
    g_ygh[md] = hh;
    g_ygl[md] = __float2bfloat16(yv - __bfloat162float(hh));
}

// ---------------- launch ----------------
extern "C" void kernel_launch(void* const* d_in, const int* in_sizes, int n_in,
                              void* d_out, int out_size)
{
    const float* x          = (const float*)d_in[0];
    const float* h          = (const float*)d_in[1];
    const float* in_proj_w  = (const float*)d_in[2];
    const float* conv1d_w   = (const float*)d_in[3];
    const float* conv1d_b   = (const float*)d_in[4];
    const float* x_proj_w   = (const float*)d_in[5];
    const float* dt_proj_w  = (const float*)d_in[6];
    const float* dt_proj_b  = (const float*)d_in[7];
    const float* A_log      = (const float*)d_in[8];
    const float* Dvec       = (const float*)d_in[9];
    const float* sf1_w      = (const float*)d_in[10];
    const float* sf1_b      = (const float*)d_in[11];
    const float* sf2_w      = (const float*)d_in[12];
    const float* sf2_b      = (const float*)d_in[13];
    const float* alpha      = (const float*)d_in[14];
    const float* out_proj_w = (const float*)d_in[15];

    float* out    = (float*)d_out;                    // [2048, 512]
    float* out_hn = (float*)d_out + (size_t)MTOK*DM;  // [2048, 1024, 16]

    float *xz, *dbc_part, *xs;
    cudaGetSymbolAddress((void**)&xz,       g_xz);
    cudaGetSymbolAddress((void**)&xs,       g_xs);
    cudaGetSymbolAddress((void**)&dbc_part, g_dBC_part);

    __nv_bfloat16 *xh, *xl, *w1h, *w1l, *w2h, *w2l, *ygh, *ygl;
    cudaGetSymbolAddress((void**)&xh,  g_xh);
    cudaGetSymbolAddress((void**)&xl,  g_xl);
    cudaGetSymbolAddress((void**)&w1h, g_w1h);
    cudaGetSymbolAddress((void**)&w1l, g_w1l);
    cudaGetSymbolAddress((void**)&w2h, g_w2h);
    cudaGetSymbolAddress((void**)&w2l, g_w2l);
    cudaGetSymbolAddress((void**)&ygh, g_ygh);
    cudaGetSymbolAddress((void**)&ygl, g_ygl);

    constexpr int SMEM_K1 = 2 * (2*128*40*2 + 2*128*40*2);   // 81920
    constexpr int SMEM_K6 = 2 * (2*64*40*2  + 2*128*40*2);   // 61440
    cudaFuncSetAttribute(mma_gemm<128,128,4,2,512>,
                         cudaFuncAttributeMaxDynamicSharedMemorySize, SMEM_K1);
    cudaFuncSetAttribute(mma_gemm<64,128,2,4,1024>,
                         cudaFuncAttributeMaxDynamicSharedMemorySize, SMEM_K6);

    // launches 1-5 (ncu -s 5 -c 1 captures the 6th launch = K1)
    negA_dtw_kernel<<<192, 256>>>(A_log, dt_proj_w);
    split_bf16_kernel<<<(DM*DI/4 + 255)/256, 256>>>(out_proj_w, w2h, w2l, DM*DI/4);
    split_bf16_kernel<<<(MTOK*DM/4 + 255)/256, 256>>>(x, xh, xl, MTOK*DM/4);
    split_bf16_kernel<<<(DI*DM/4 + 255)/256, 256>>>(in_proj_w, w1h, w1l, DI*DM/4);
    split_bf16_kernel<<<(DI*DM/4 + 255)/256, 256>>>(in_proj_w + (size_t)DI*DM,
                                                    w1h + (size_t)DI*DM,
                                                    w1l + (size_t)DI*DM, DI*DM/4);

    // K1: xz = x @ in_proj_w^T  [2048,2048,K=512] — HMMA bf16x3
    mma_gemm<128,128,4,2,512><<<dim3(2*DI/128, MTOK/128), 256, SMEM_K1>>>(
        xh, xl, w1h, w1l, xz, 2*DI);

    // K2: xs = silu(dwconv1d(xc))
    conv_silu_kernel<<<dim3(4, MTOK), 256>>>(conv1d_w, conv1d_b);

    // K3: dBC = xs @ x_proj_w^T  (split-K x8)
    gemm_nt_splitk<64,64,16,4,4,128><<<dim3(KSPLIT, MTOK/64), 256>>>(
        xs, x_proj_w, dbc_part, DI, DI);
    splitk_reduce_kernel<<<(MTOK*32 + 255)/256, 256>>>();

    // K5: fused delta + SSM + state fusion + y + gate
    ssm_fused_kernel<<<dim3(4, MTOK), 256>>>(
        h, dt_proj_b, Dvec, sf1_w, sf1_b, sf2_w, sf2_b, alpha, out_hn);

    // K6: out = (y * silu(z)) @ out_proj_w^T — HMMA bf16x3
    mma_gemm<64,128,2,4,1024><<<dim3(DM/128, MTOK/64), 256, SMEM_K6>>>(
        ygh, ygl, w2h, w2l, out, DM);
}

// round 9
// speedup vs baseline: 1.2604x; 1.0193x over previous
#include <cuda_runtime.h>
#include <cuda_bf16.h>
#include <math.h>
#include <stdint.h>

// ---------------- problem constants ----------------
#define BB 2
#define LL 1024
#define DM 512
#define DI 1024
#define RK 32
#define NS 16
#define MTOK (BB*LL)          // 2048 tokens
#define KSPLIT 8              // split-K factor for x_proj GEMM

// ---------------- scratch (static device arrays; no dynamic alloc) ---------
__device__ __align__(16) float g_xz[MTOK * 2 * DI];
__device__ __align__(16) float g_xs[MTOK * DI];
__device__ __align__(16) float g_dBC[MTOK * 64];
__device__ __align__(16) float g_dBC_part[KSPLIT * MTOK * 64];
__device__ __align__(16) float g_negA[DI * NS];
__device__ __align__(16) float g_dtwT[RK * DI];         // dt_proj_w transposed [32][1024]
// bf16 hi/lo split buffers for tensor-core GEMMs
__device__ __align__(16) __nv_bfloat16 g_xh[MTOK * DM],  g_xl[MTOK * DM];
__device__ __align__(16) __nv_bfloat16 g_w1h[2*DI * DM], g_w1l[2*DI * DM];
__device__ __align__(16) __nv_bfloat16 g_w2h[DM * DI],   g_w2l[DM * DI];
__device__ __align__(16) __nv_bfloat16 g_ygh[MTOK * DI], g_ygl[MTOK * DI];

// ---------------- PTX helpers (arch-portable: sm_80+) ----------------
__device__ __forceinline__ uint32_t smem_u32(const void* p) {
    uint32_t a;
    asm("{ .reg .u64 t; cvta.to.shared.u64 t, %1; cvt.u32.u64 %0, t; }"
        : "=r"(a) : "l"(p));
    return a;
}

__device__ __forceinline__ void cp16(uint32_t saddr, const void* gptr) {
    asm volatile("cp.async.ca.shared.global [%0], [%1], 16;"
                 :: "r"(saddr), "l"(gptr));
}

__device__ __forceinline__ void ldsm_x4(uint32_t& r0, uint32_t& r1,
                                        uint32_t& r2, uint32_t& r3, uint32_t addr) {
    asm volatile("ldmatrix.sync.aligned.m8n8.x4.shared.b16 {%0,%1,%2,%3}, [%4];"
                 : "=r"(r0), "=r"(r1), "=r"(r2), "=r"(r3) : "r"(addr));
}

__device__ __forceinline__ void mma16816(float* d, const uint32_t* a, const uint32_t* b) {
    asm volatile(
        "mma.sync.aligned.m16n8k16.row.col.f32.bf16.bf16.f32 "
        "{%0,%1,%2,%3}, {%4,%5,%6,%7}, {%8,%9}, {%0,%1,%2,%3};"
        : "+f"(d[0]), "+f"(d[1]), "+f"(d[2]), "+f"(d[3])
        : "r"(a[0]), "r"(a[1]), "r"(a[2]), "r"(a[3]), "r"(b[0]), "r"(b[1]));
}

// ============ HMMA GEMM: C[M,N] = (Ah+Al)[M,K] * (Bh+Bl)[N,K]^T ============
// bf16x3 split: Ah*Bh + Ah*Bl + Al*Bh, fp32 accum. cp.async 2-stage pipeline.
template<int BM, int BN, int WMG, int WNG, int KTOT>
__global__ void __launch_bounds__(256)
mma_gemm(const __nv_bfloat16* __restrict__ Ah, const __nv_bfloat16* __restrict__ Al,
         const __nv_bfloat16* __restrict__ Bh, const __nv_bfloat16* __restrict__ Bl,
         float* __restrict__ C, int ldc)
{
    constexpr int BK  = 32;
    constexpr int LDT = 40;                 // smem row stride in bf16 (80B)
    constexpr int ATB = BM * LDT * 2;
    constexpr int BTB = BN * LDT * 2;
    constexpr int STAGE = 2*ATB + 2*BTB;
    constexpr int NIT = KTOT / BK;
    constexpr int WTM = BM / WMG;
    constexpr int WTN = BN / WNG;
    constexpr int MT  = WTM / 16;
    constexpr int NT  = WTN / 8;

    extern __shared__ char smem[];
    const uint32_t sbase = smem_u32(smem);
    const int tid  = threadIdx.x;
    const int lane = tid & 31;
    const int wid  = tid >> 5;
    const int wm   = wid % WMG;
    const int wn   = wid / WMG;
    const int row0 = blockIdx.y * BM;
    const int col0 = blockIdx.x * BN;

    float acc[MT][NT][4];
    #pragma unroll
    for (int i = 0; i < MT; i++)
        #pragma unroll
        for (int j = 0; j < NT; j++)
            #pragma unroll
            for (int q = 0; q < 4; q++) acc[i][j][q] = 0.f;

    auto load_stage = [&](int kb, int s) {
        const int k0 = kb * BK;
        const uint32_t sa = sbase + (uint32_t)s * STAGE;
        for (int i = tid; i < BM*4; i += 256) {
            int r = i >> 2, c = i & 3;
            uint32_t off = (uint32_t)r * (LDT*2) + c*16;
            cp16(sa + off,       Ah + (size_t)(row0+r)*KTOT + k0 + c*8);
            cp16(sa + ATB + off, Al + (size_t)(row0+r)*KTOT + k0 + c*8);
        }
        for (int i = tid; i < BN*4; i += 256) {
            int r = i >> 2, c = i & 3;
            uint32_t off = (uint32_t)r * (LDT*2) + c*16;
            cp16(sa + 2*ATB + off,       Bh + (size_t)(col0+r)*KTOT + k0 + c*8);
            cp16(sa + 2*ATB + BTB + off, Bl + (size_t)(col0+r)*KTOT + k0 + c*8);
        }
        asm volatile("cp.async.commit_group;" ::: "memory");
    };

    load_stage(0, 0);

    for (int kb = 0; kb < NIT; kb++) {
        if (kb + 1 < NIT) {
            load_stage(kb+1, (kb+1) & 1);
            asm volatile("cp.async.wait_group 1;" ::: "memory");
        } else {
            asm volatile("cp.async.wait_group 0;" ::: "memory");
        }
        __syncthreads();

        const uint32_t stA  = sbase + (uint32_t)(kb & 1) * STAGE;
        const uint32_t stAl = stA + ATB;
        const uint32_t stBh = stA + 2*ATB;
        const uint32_t stBl = stA + 2*ATB + BTB;

        #pragma unroll
        for (int ks = 0; ks < 2; ks++) {
            uint32_t ah[MT][4], al[MT][4], bh[NT][2], bl[NT][2];
            #pragma unroll
            for (int mt = 0; mt < MT; mt++) {
                int ar = wm*WTM + mt*16 + (lane & 15);
                int ac = ks*16 + (lane >> 4) * 8;
                uint32_t off = (uint32_t)ar*(LDT*2) + ac*2;
                ldsm_x4(ah[mt][0], ah[mt][1], ah[mt][2], ah[mt][3], stA  + off);
                ldsm_x4(al[mt][0], al[mt][1], al[mt][2], al[mt][3], stAl + off);
            }
            #pragma unroll
            for (int p = 0; p < NT/2; p++) {
                int br = wn*WTN + p*16 + (lane >> 4)*8 + (lane & 7);
                int bc = ks*16 + ((lane >> 3) & 1) * 8;
                uint32_t off = (uint32_t)br*(LDT*2) + bc*2;
                ldsm_x4(bh[2*p][0], bh[2*p][1], bh[2*p+1][0], bh[2*p+1][1], stBh + off);
                ldsm_x4(bl[2*p][0], bl[2*p][1], bl[2*p+1][0], bl[2*p+1][1], stBl + off);
            }
            #pragma unroll
            for (int mt = 0; mt < MT; mt++)
                #pragma unroll
                for (int nt = 0; nt < NT; nt++) {
                    mma16816(acc[mt][nt], ah[mt], bh[nt]);
                    mma16816(acc[mt][nt], ah[mt], bl[nt]);
                    mma16816(acc[mt][nt], al[mt], bh[nt]);
                }
        }
        __syncthreads();
    }

    #pragma unroll
    for (int mt = 0; mt < MT; mt++) {
        int r = row0 + wm*WTM + mt*16 + (lane >> 2);
        #pragma unroll
        for (int nt = 0; nt < NT; nt++) {
            int c = col0 + wn*WTN + nt*8 + (lane & 3)*2;
            *reinterpret_cast<float2*>(&C[(size_t)r*ldc + c]) =
                make_float2(acc[mt][nt][0], acc[mt][nt][1]);
            *reinterpret_cast<float2*>(&C[(size_t)(r+8)*ldc + c]) =
                make_float2(acc[mt][nt][2], acc[mt][nt][3]);
        }
    }
}

// ================= scalar helpers =================
union F2 { unsigned long long u; float2 f; };

__device__ __forceinline__ void ffma2(F2& d, const F2& a, const F2& b) {
    asm("fma.rn.f32x2 %0, %1, %2, %0;" : "+l"(d.u) : "l"(a.u), "l"(b.u));
}

__device__ __forceinline__ float softplusf(float v) {
    return (v > 20.f) ? v : log1pf(expf(v));
}
__device__ __forceinline__ float siluf(float v) {
    return v / (1.f + __expf(-v));
}

__device__ __forceinline__ void split4(const float* __restrict__ src,
                                       __nv_bfloat16* __restrict__ hi,
                                       __nv_bfloat16* __restrict__ lo, int i)
{
    float4 v = ((const float4*)src)[i];
    __nv_bfloat16 h0 = __float2bfloat16(v.x), h1 = __float2bfloat16(v.y);
    __nv_bfloat16 h2 = __float2bfloat16(v.z), h3 = __float2bfloat16(v.w);
    __nv_bfloat16 l0 = __float2bfloat16(v.x - __bfloat162float(h0));
    __nv_bfloat16 l1 = __float2bfloat16(v.y - __bfloat162float(h1));
    __nv_bfloat16 l2 = __float2bfloat16(v.z - __bfloat162float(h2));
    __nv_bfloat16 l3 = __float2bfloat16(v.w - __bfloat162float(h3));
    *(__nv_bfloat162*)(hi + 4*i)     = __nv_bfloat162(h0, h1);
    *(__nv_bfloat162*)(hi + 4*i + 2) = __nv_bfloat162(h2, h3);
    *(__nv_bfloat162*)(lo + 4*i)     = __nv_bfloat162(l0, l1);
    *(__nv_bfloat162*)(lo + 4*i + 2) = __nv_bfloat162(l2, l3);
}

// ---------------- one-launch prep: all splits + negA + dtwT ----------------
// regions (in work-item units):
//   [0, 131072)        out_proj_w float4 split -> w2h/w2l
//   [131072, 393216)   x           float4 split -> xh/xl
//   [393216, 655360)   in_proj_w   float4 split -> w1h/w1l
//   [655360, 671744)   negA element
//   [671744, 704512)   dtwT element
__global__ void prep_all_kernel(const float* __restrict__ x,
                                const float* __restrict__ in_proj_w,
                                const float* __restrict__ out_proj_w,
                                const float* __restrict__ A_log,
                                const float* __restrict__ dtw)
{
    int gi = blockIdx.x * 256 + threadIdx.x;
    if (gi < 131072) {
        split4(out_proj_w, g_w2h, g_w2l, gi);
    } else if (gi < 393216) {
        split4(x, g_xh, g_xl, gi - 131072);
    } else if (gi < 655360) {
        split4(in_proj_w, g_w1h, g_w1l, gi - 393216);
    } else if (gi < 671744) {
        int i = gi - 655360;
        g_negA[i] = -expf(A_log[i]);
    } else if (gi < 704512) {
        int i = gi - 671744;          // transposed index: k*DI + d
        int k = i / DI, d = i % DI;
        g_dtwT[i] = dtw[(size_t)d * RK + k];
    }
}

// ---------------- depthwise conv1d (K=3, SAME) + silu ----------------
__global__ void conv_silu_kernel(const float* __restrict__ w,
                                 const float* __restrict__ b)
{
    int d = blockIdx.x * blockDim.x + threadIdx.x;
    int m = blockIdx.y;
    int l = m & (LL - 1);
    float w0 = w[d*3+0], w1 = w[d*3+1], w2 = w[d*3+2];
    float xm = (l > 0)      ? g_xz[(size_t)(m-1)*2*DI + d] : 0.f;
    float x0 =                g_xz[(size_t)m    *2*DI + d];
    float xp = (l < LL-1)   ? g_xz[(size_t)(m+1)*2*DI + d] : 0.f;
    float v = fmaf(w0, xm, fmaf(w1, x0, fmaf(w2, xp, b[d])));
    g_xs[(size_t)m*DI + d] = siluf(v);
}

// ---------------- split-K NT GEMM for skinny x_proj ----------------
template<int BM, int BN, int BK, int TM, int TN, int KC>
__global__ void __launch_bounds__((BM/TM)*(BN/TN))
gemm_nt_splitk(const float* __restrict__ A, const float* __restrict__ B,
               float* __restrict__ Cpart, int lda, int ldb)
{
    constexpr int THREADS = (BM/TM) * (BN/TN);
    constexpr int TXN = BN / TN;
    __shared__ __align__(16) float As[BK][BM];
    __shared__ __align__(16) float Bs[BK][BN];

    const int tid = threadIdx.x;
    const int tx  = tid % TXN;
    const int ty  = tid / TXN;
    const int row0   = blockIdx.y * BM;
    const int kchunk = blockIdx.x;
    const int kbase  = kchunk * KC;

    F2 acc[TM][TN/2];
    #pragma unroll
    for (int i = 0; i < TM; i++)
        #pragma unroll
        for (int j = 0; j < TN/2; j++) { acc[i][j].f.x = 0.f; acc[i][j].f.y = 0.f; }

    for (int k0 = kbase; k0 < kbase + KC; k0 += BK) {
        #pragma unroll
        for (int i = tid; i < BM*BK/4; i += THREADS) {
            int r = i / (BK/4), cv = i % (BK/4);
            float4 v = *reinterpret_cast<const float4*>(
                &A[(size_t)(row0 + r) * lda + k0 + cv*4]);
            As[cv*4+0][r] = v.x; As[cv*4+1][r] = v.y;
            As[cv*4+2][r] = v.z; As[cv*4+3][r] = v.w;
        }
        #pragma unroll
        for (int i = tid; i < BN*BK/4; i += THREADS) {
            int r = i / (BK/4), cv = i % (BK/4);
            float4 v = *reinterpret_cast<const float4*>(
                &B[(size_t)r * ldb + k0 + cv*4]);
            Bs[cv*4+0][r] = v.x; Bs[cv*4+1][r] = v.y;
            Bs[cv*4+2][r] = v.z; Bs[cv*4+3][r] = v.w;
        }
        __syncthreads();

        #pragma unroll
        for (int k = 0; k < BK; k++) {
            float a_frag[TM];
            F2 b_frag[TN/2];
            #pragma unroll
            for (int i = 0; i < TM; i++) a_frag[i] = As[k][ty*TM + i];
            #pragma unroll
            for (int j = 0; j < TN/2; j++)
                b_frag[j] = *reinterpret_cast<const F2*>(&Bs[k][tx*TN + 2*j]);
            #pragma unroll
            for (int i = 0; i < TM; i++) {
                F2 ad; ad.f.x = a_frag[i]; ad.f.y = a_frag[i];
                #pragma unroll
                for (int j = 0; j < TN/2; j++) ffma2(acc[i][j], ad, b_frag[j]);
            }
        }
        __syncthreads();
    }

    float* Cp = Cpart + (size_t)kchunk * MTOK * 64;
    #pragma unroll
    for (int i = 0; i < TM; i++) {
        int r = row0 + ty*TM + i;
        #pragma unroll
        for (int j = 0; j < TN/2; j++) {
            int c = tx*TN + 2*j;
            *reinterpret_cast<float2*>(&Cp[(size_t)r * 64 + c]) = acc[i][j].f;
        }
    }
}

__global__ void splitk_reduce_kernel() {
    int i = blockIdx.x * blockDim.x + threadIdx.x;
    if (i >= MTOK * 32) return;
    float2 s = make_float2(0.f, 0.f);
    #pragma unroll
    for (int c = 0; c < KSPLIT; c++) {
        float2 v = *reinterpret_cast<const float2*>(&g_dBC_part[(size_t)c*MTOK*64 + i*2]);
        s.x += v.x; s.y += v.y;
    }
    *reinterpret_cast<float2*>(&g_dBC[i*2]) = s;
}

// ---- fused: delta(coalesced dtwT dot) + SSM + state fusion + y + gate -----
__global__ void ssm_fused_kernel(const float* __restrict__ h,
                                 const float* __restrict__ dtb,
                                 const float* __restrict__ Dvec,
                                 const float* __restrict__ sf1w,
                                 const float* __restrict__ sf1b,
                                 const float* __restrict__ sf2w,
                                 const float* __restrict__ sf2b,
                                 const float* __restrict__ alpha,
                                 float* __restrict__ out_hn)
{
    int d = blockIdx.x * blockDim.x + threadIdx.x;
    int m = blockIdx.y;
    size_t md = (size_t)m * DI + d;

    __shared__ float dbc_s[64];
    if (threadIdx.x < 64) dbc_s[threadIdx.x] = g_dBC[(size_t)m * 64 + threadIdx.x];
    __syncthreads();

    // delta = softplus(dBC[m,0:32] . dtwT[:,d] + dtb[d]) — coalesced over d
    float acc = dtb[d];
    #pragma unroll
    for (int k = 0; k < RK; k++)
        acc = fmaf(g_dtwT[k*DI + d], dbc_s[k], acc);
    float dv  = softplusf(acc);
    float xsv = g_xs[md];
    float dx  = dv * xsv;

    const float4* hp = reinterpret_cast<const float4*>(h + md * NS);
    float hn[16];
    #pragma unroll
    for (int q = 0; q < 4; q++) {
        float4 hv = hp[q];
        float na0 = g_negA[d*NS + 4*q + 0];
        float na1 = g_negA[d*NS + 4*q + 1];
        float na2 = g_negA[d*NS + 4*q + 2];
        float na3 = g_negA[d*NS + 4*q + 3];
        hn[4*q+0] = fmaf(__expf(dv*na0), hv.x, dx * dbc_s[32 + 4*q + 0]);
        hn[4*q+1] = fmaf(__expf(dv*na1), hv.y, dx * dbc_s[32 + 4*q + 1]);
        hn[4*q+2] = fmaf(__expf(dv*na2), hv.z, dx * dbc_s[32 + 4*q + 2]);
        hn[4*q+3] = fmaf(__expf(dv*na3), hv.w, dx * dbc_s[32 + 4*q + 3]);
    }

    float a0 = alpha[0], a1 = alpha[1];
    float c1 = a0 * sf1w[d];
    float cb = fmaf(a0, sf1b[d], a1 * sf2b[d]);
    float w[9];
    #pragma unroll
    for (int i = 0; i < 9; i++) w[i] = sf2w[d*9 + i];

    float y = 0.f;
    float hf[16];
    #pragma unroll
    for (int r = 0; r < 4; r++) {
        #pragma unroll
        for (int c = 0; c < 4; c++) {
            float a2 = 0.f;
            #pragma unroll
            for (int ii = 0; ii < 3; ii++) {
                int rr = r + ii - 1;
                if (rr < 0 || rr > 3) continue;
                #pragma unroll
                for (int jj = 0; jj < 3; jj++) {
                    int cc = c + jj - 1;
                    if (cc < 0 || cc > 3) continue;
                    a2 = fmaf(w[ii*3 + jj], hn[rr*4 + cc], a2);
                }
            }
            float v = fmaf(c1, hn[r*4 + c], fmaf(a1, a2, cb));
            hf[r*4 + c] = v;
            y = fmaf(v, dbc_s[48 + r*4 + c], y);
        }
    }

    float4* op = reinterpret_cast<float4*>(out_hn + md * NS);
    #pragma unroll
    for (int q = 0; q < 4; q++)
        op[q] = make_float4(hf[4*q+0], hf[4*q+1], hf[4*q+2], hf[4*q+3]);

    y = fmaf(Dvec[d], xsv, y);
    float zv = g_xz[(size_t)m * 2 * DI + DI + d];
    float yv = y * siluf(zv);
    __nv_bfloat16 hh = __float2bfloat16(yv);
    g_ygh[md] = hh;
    g_ygl[md] = __float2bfloat16(yv - __bfloat162float(hh));
}

// ---------------- launch ----------------
extern "C" void kernel_launch(void* const* d_in, const int* in_sizes, int n_in,
                              void* d_out, int out_size)
{
    const float* x          = (const float*)d_in[0];
    const float* h          = (const float*)d_in[1];
    const float* in_proj_w  = (const float*)d_in[2];
    const float* conv1d_w   = (const float*)d_in[3];
    const float* conv1d_b   = (const float*)d_in[4];
    const float* x_proj_w   = (const float*)d_in[5];
    const float* dt_proj_w  = (const float*)d_in[6];
    const float* dt_proj_b  = (const float*)d_in[7];
    const float* A_log      = (const float*)d_in[8];
    const float* Dvec       = (const float*)d_in[9];
    const float* sf1_w      = (const float*)d_in[10];
    const float* sf1_b      = (const float*)d_in[11];
    const float* sf2_w      = (const float*)d_in[12];
    const float* sf2_b      = (const float*)d_in[13];
    const float* alpha      = (const float*)d_in[14];
    const float* out_proj_w = (const float*)d_in[15];

    float* out    = (float*)d_out;                    // [2048, 512]
    float* out_hn = (float*)d_out + (size_t)MTOK*DM;  // [2048, 1024, 16]

    float *xz, *dbc_part, *xs;
    cudaGetSymbolAddress((void**)&xz,       g_xz);
    cudaGetSymbolAddress((void**)&xs,       g_xs);
    cudaGetSymbolAddress((void**)&dbc_part, g_dBC_part);

    __nv_bfloat16 *xh, *xl, *w1h, *w1l, *w2h, *w2l, *ygh, *ygl;
    cudaGetSymbolAddress((void**)&xh,  g_xh);
    cudaGetSymbolAddress((void**)&xl,  g_xl);
    cudaGetSymbolAddress((void**)&w1h, g_w1h);
    cudaGetSymbolAddress((void**)&w1l, g_w1l);
    cudaGetSymbolAddress((void**)&w2h, g_w2h);
    cudaGetSymbolAddress((void**)&w2l, g_w2l);
    cudaGetSymbolAddress((void**)&ygh, g_ygh);
    cudaGetSymbolAddress((void**)&ygl, g_ygl);

    // K1: <128,64> 2 stages * (2*128*80 + 2*64*80) = 61440 B, grid 512
    // K6: <64,64>  2 stages * (2*64*80  + 2*64*80) = 40960 B, grid 256
    constexpr int SMEM_K1 = 2 * (2*128*40*2 + 2*64*40*2);
    constexpr int SMEM_K6 = 2 * (2*64*40*2  + 2*64*40*2);
    cudaFuncSetAttribute(mma_gemm<128,64,4,2,512>,
                         cudaFuncAttributeMaxDynamicSharedMemorySize, SMEM_K1);
    cudaFuncSetAttribute(mma_gemm<64,64,2,4,1024>,
                         cudaFuncAttributeMaxDynamicSharedMemorySize, SMEM_K6);

    // L1: all prep in one launch (704512 work items)
    prep_all_kernel<<<2752, 256>>>(x, in_proj_w, out_proj_w, A_log, dt_proj_w);

    // L2 (K1): xz = x @ in_proj_w^T  [2048,2048,K=512] — HMMA bf16x3, BN=64
    mma_gemm<128,64,4,2,512><<<dim3(2*DI/64, MTOK/128), 256, SMEM_K1>>>(
        xh, xl, w1h, w1l, xz, 2*DI);

    // L3 (K2): xs = silu(dwconv1d(xc))
    conv_silu_kernel<<<dim3(4, MTOK), 256>>>(conv1d_w, conv1d_b);

    // L4 (K3): dBC = xs @ x_proj_w^T  (split-K x8)
    gemm_nt_splitk<64,64,16,4,4,128><<<dim3(KSPLIT, MTOK/64), 256>>>(
        xs, x_proj_w, dbc_part, DI, DI);
    // L5: reduce
    splitk_reduce_kernel<<<(MTOK*32 + 255)/256, 256>>>();

    // L6 (K5): fused delta + SSM + state fusion + y + gate
    ssm_fused_kernel<<<dim3(4, MTOK), 256>>>(
        h, dt_proj_b, Dvec, sf1_w, sf1_b, sf2_w, sf2_b, alpha, out_hn);

    // L7 (K6): out = (y * silu(z)) @ out_proj_w^T — HMMA bf16x3, BN=64
    mma_gemm<64,64,2,4,1024><<<dim3(DM/64, MTOK/64), 256, SMEM_K6>>>(
        ygh, ygl, w2h, w2l, out, DM);
}